// round 13
// baseline (speedup 1.0000x reference)
#include <cuda_runtime.h>
#include <math.h>

// ---------------- problem constants ----------------
#define BB   2048          // graphs
#define NP   68            // nodes per graph
#define NC   8             // clusters
#define FH   128           // hidden
#define NN   (BB*NP)       // 139264 nodes
#define EE   (BB*NP*8)     // 1114112 edges
#define EPG  (NP*8)        // 544 edges per graph
#define NRG  (NN/8)        // 17408 row-groups of 8
#define NWU  (2*NRG)       // 34816 warp work units (row-group x col-half)

typedef unsigned long long ull;

// ---------------- scratch (device globals: no allocation allowed) ----------------
__device__ float g_P [(size_t)NN*FH];   // H @ W_rel
__device__ float g_Rb[(size_t)NN*FH];   // H @ W_root + b
__device__ float g_HA[(size_t)NN*FH];
__device__ float g_HB[(size_t)NN*FH];
__device__ int   g_is64;
// CSR: per-node in-edge lists (local src ids)
__device__ int           g_cnt[NN];
__device__ int           g_off[NN];
__device__ int           g_cur[NN];
__device__ unsigned char g_srcs[EE];
// k-pair-major packed weights: [layer][kp*256 + f] = (W[2kp][f], W[2kp+1][f]),
// f<128 -> Wrel, f>=128 -> Wroot
__device__ float2 g_WP[2][64*256];

// ---------------- f32x2 packed helpers ----------------
__device__ __forceinline__ void fma2(ull& d, ull a, ull b){
    asm("fma.rn.f32x2 %0, %1, %2, %0;" : "+l"(d) : "l"(a), "l"(b));
}
__device__ __forceinline__ ull dup2(float x){
    ull r; asm("mov.b64 %0, {%1, %1};" : "=l"(r) : "f"(x)); return r;
}
__device__ __forceinline__ float2 unpack2(ull v){
    float2 f; asm("mov.b64 {%0, %1}, %2;" : "=f"(f.x), "=f"(f.y) : "l"(v)); return f;
}

// ---------------- init: zero counts + edge dtype detect (int64 high words zero) ----------------
__global__ void k_init(const int* __restrict__ ei){
    int i = blockIdx.x*blockDim.x + threadIdx.x;
    if (i < NN) g_cnt[i] = 0;
    if (blockIdx.x == 0){
        __shared__ int anynz;
        if (threadIdx.x == 0) anynz = 0;
        __syncthreads();
        if (ei[2*threadIdx.x + 1] != 0) atomicOr(&anynz, 1);
        __syncthreads();
        if (threadIdx.x == 0) g_is64 = (anynz == 0) ? 1 : 0;
    }
}

__global__ void k_count(const int* __restrict__ ei){
    const int is64 = g_is64;
    int e = blockIdx.x*blockDim.x + threadIdx.x;
    if (e >= EE) return;
    int d = is64 ? ei[2*(EE + e)] : ei[EE + e];
    atomicAdd(&g_cnt[d], 1);
}

// exclusive scan per graph via warp shfl-scan (1 warp = 1 graph)
__global__ void k_offs(){
    const int g = blockIdx.x*8 + (threadIdx.x >> 5);
    const int lane = threadIdx.x & 31;
    if (g >= BB) return;
    const int base = g * EPG;
    int carry = 0;
    #pragma unroll
    for (int ch = 0; ch < 3; ch++){
        int n = ch*32 + lane;
        int valid = (n < NP);
        int v0 = valid ? g_cnt[g*NP + n] : 0;
        int v = v0;
        #pragma unroll
        for (int o = 1; o < 32; o <<= 1){
            int x = __shfl_up_sync(0xffffffffu, v, o);
            if (lane >= o) v += x;
        }
        if (valid){
            int off = base + carry + v - v0;
            g_off[g*NP + n] = off;
            g_cur[g*NP + n] = off;
        }
        carry += __shfl_sync(0xffffffffu, v, 31);
    }
}

__global__ void k_scatter(const int* __restrict__ ei){
    const int is64 = g_is64;
    int e = blockIdx.x*blockDim.x + threadIdx.x;
    if (e >= EE) return;
    int s, d;
    if (is64){ s = ei[2*e]; d = ei[2*(EE + e)]; }
    else     { s = ei[e];   d = ei[EE + e];    }
    int gs = s / NP;  int ls = s - gs*NP;
    int pos = atomicAdd(&g_cur[d], 1);
    g_srcs[pos] = (unsigned char)ls;
}

// deterministic order: insertion-sort each node's src list
__global__ void k_sortsrc(){
    int n = blockIdx.x*blockDim.x + threadIdx.x;
    if (n >= NN) return;
    int off = g_off[n], c = g_cnt[n];
    for (int i = 1; i < c; i++){
        unsigned char key = g_srcs[off+i];
        int j = i - 1;
        while (j >= 0 && g_srcs[off+j] > key){ g_srcs[off+j+1] = g_srcs[off+j]; j--; }
        g_srcs[off+j+1] = key;
    }
}

// ---------------- W prep: k-pair-major packing ----------------
__global__ void k_prepW(const float* __restrict__ Wre2, const float* __restrict__ Wro2,
                        const float* __restrict__ Wre3, const float* __restrict__ Wro3){
    int idx = blockIdx.x*blockDim.x + threadIdx.x;   // 0 .. 32767
    int layer = idx >> 14;
    int r = idx & 16383;
    int kp = r >> 8, f = r & 255;
    const float* Wrel  = layer ? Wre3 : Wre2;
    const float* Wroot = layer ? Wro3 : Wro2;
    int k = kp*2;
    float v0, v1;
    if (f < 128){ v0 = Wrel[k*128 + f];        v1 = Wrel[(k+1)*128 + f]; }
    else        { v0 = Wroot[k*128 + (f-128)]; v1 = Wroot[(k+1)*128 + (f-128)]; }
    g_WP[layer][r] = make_float2(v0, v1);
}

// ---------------- layer 1 (F_IN = 2): HA = relu(agg@Wrel + x@Wroot + b) ----------------
__global__ void k_layer1(const float* __restrict__ x,
                         const float* __restrict__ Wrel, const float* __restrict__ Wroot,
                         const float* __restrict__ b){
    __shared__ float xs[NP*2], ax[NP*2], wr[2*FH], wo[2*FH], bs[FH];
    const int g = blockIdx.x, t = threadIdx.x;
    if (t < NP*2) xs[t] = x[(size_t)g*NP*2 + t];
    if (t < FH){
        wr[t] = Wrel[t];  wr[FH+t] = Wrel[FH+t];
        wo[t] = Wroot[t]; wo[FH+t] = Wroot[FH+t];
        bs[t] = b[t];
    }
    __syncthreads();
    if (t < NP*2){
        int n = t >> 1, d = t & 1;
        int off = g_off[g*NP + n], cnt = g_cnt[g*NP + n];
        float sv = 0.0f;
        for (int i = 0; i < cnt; i++) sv += xs[((int)g_srcs[off+i])*2 + d];
        ax[t] = sv;
    }
    __syncthreads();
    for (int idx = t; idx < NP*FH; idx += blockDim.x){
        int n = idx >> 7, f = idx & 127;
        float v = ax[n*2]*wr[f] + ax[n*2+1]*wr[FH+f]
                + xs[n*2]*wo[f] + xs[n*2+1]*wo[FH+f] + bs[f];
        g_HA[(size_t)g*NP*FH + idx] = fmaxf(v, 0.0f);
    }
}

// ---------------- zero-smem dual GEMM: P = H@Wrel, Rb = H@Wroot + b ----------------
// Each warp owns one work unit: 8 rows x one 128-col half. A loads are warp-broadcast
// LDG.64 (each element read once per warp); W loads are coalesced 256B LDG.64 from the
// L1-resident k-pair-major pack. No shared memory, no barriers; 16 warps/SM.
__global__ void __launch_bounds__(128, 4) k_gemm0(int layer, const float* __restrict__ bias){
    const float* __restrict__ Hin = (layer == 2) ? g_HA : g_HB;
    const float2* __restrict__ WP = g_WP[layer-2];
    const int w = threadIdx.x >> 5, c = threadIdx.x & 31;
    const int nw = gridDim.x * 4;

    for (int wid = blockIdx.x*4 + w; wid < NWU; wid += nw){
        const int rg = wid >> 1, half = wid & 1;
        const float* __restrict__ A = Hin + (size_t)rg*8*128;
        const float2* __restrict__ wp = WP + half*128 + c;

        ull acc[8][4];
        #pragma unroll
        for (int i = 0; i < 8; i++)
            #pragma unroll
            for (int j = 0; j < 4; j++) acc[i][j] = 0ULL;

        #pragma unroll 2
        for (int kp = 0; kp < 64; kp++){
            ull a[8], b[4];
            #pragma unroll
            for (int i = 0; i < 8; i++)
                a[i] = *(const ull*)(A + i*128 + 2*kp);
            #pragma unroll
            for (int j = 0; j < 4; j++)
                b[j] = *(const ull*)(wp + kp*256 + 32*j);
            #pragma unroll
            for (int i = 0; i < 8; i++)
                #pragma unroll
                for (int j = 0; j < 4; j++)
                    fma2(acc[i][j], a[i], b[j]);
        }

        if (half == 0){
            #pragma unroll
            for (int i = 0; i < 8; i++){
                float* dst = g_P + ((size_t)rg*8 + i)*128 + c;
                #pragma unroll
                for (int j = 0; j < 4; j++){
                    float2 p = unpack2(acc[i][j]);
                    dst[32*j] = p.x + p.y;
                }
            }
        } else {
            float bv[4];
            #pragma unroll
            for (int j = 0; j < 4; j++) bv[j] = __ldg(bias + c + 32*j);
            #pragma unroll
            for (int i = 0; i < 8; i++){
                float* dst = g_Rb + ((size_t)rg*8 + i)*128 + c;
                #pragma unroll
                for (int j = 0; j < 4; j++){
                    float2 p = unpack2(acc[i][j]);
                    dst[32*j] = p.x + p.y + bv[j];
                }
            }
        }
    }
}

// ---------------- conv-apply (sparse): H_out = relu(sum_{j->n} P_j + Rb_n) ----------------
#define PST 130
__global__ void __launch_bounds__(544) k_conv(int layer){
    __shared__ float Ps[NP*PST];
    const int g = blockIdx.x, t = threadIdx.x;
    float* __restrict__ Hout = (layer == 2) ? g_HB : g_HA;

    const float* Pg = g_P + (size_t)g*NP*FH;
    for (int i = t; i < NP*FH; i += 544){
        int row = i >> 7, col = i & 127;
        Ps[row*PST + col] = Pg[i];
    }
    __syncthreads();

    const int n  = t >> 3;     // 0..67
    const int cg = t & 7;      // 0..7 -> pair cols cg + 8u
    const int off = g_off[g*NP + n];
    const int cnt = g_cnt[g*NP + n];

    const float* rb = g_Rb + ((size_t)g*NP + n)*FH;
    ull acc[8];
    #pragma unroll
    for (int u = 0; u < 8; u++) acc[u] = *(const ull*)(rb + 2*(cg + 8*u));

    const ull one = dup2(1.0f);
    for (int e = 0; e < cnt; e++){
        const float* pr = Ps + ((int)g_srcs[off+e])*PST;
        #pragma unroll
        for (int u = 0; u < 8; u++){
            ull pv = *(const ull*)(pr + 2*(cg + 8*u));
            fma2(acc[u], one, pv);
        }
    }
    float* ho = Hout + ((size_t)g*NP + n)*FH;
    #pragma unroll
    for (int u = 0; u < 8; u++){
        float2 v = unpack2(acc[u]);
        v.x = fmaxf(v.x, 0.0f); v.y = fmaxf(v.y, 0.0f);
        *(float2*)(ho + 2*(cg + 8*u)) = v;
    }
}

// ---------------- pool: softmax(s) einsum, maxpool(1,8), fc ----------------
__global__ void __launch_bounds__(512) k_pool(const float* __restrict__ s_in,
                       const float* __restrict__ fcw, const float* __restrict__ fcb,
                       float* __restrict__ out){
    __shared__ float Hs[NP*FH];
    __shared__ float ssm[NP*NC];
    __shared__ float xp[NC*FH];
    __shared__ float red[128];
    const int g = blockIdx.x, t = threadIdx.x;

    const float* Hg = g_HA + (size_t)g*NP*FH;
    for (int i = t; i < NP*FH; i += 512) Hs[i] = Hg[i];

    if (t < NP){
        float v[NC]; float m = -1e30f;
        #pragma unroll
        for (int k = 0; k < NC; k++){ v[k] = s_in[((size_t)g*NP + t)*NC + k]; m = fmaxf(m, v[k]); }
        float sum = 0.0f;
        #pragma unroll
        for (int k = 0; k < NC; k++){ v[k] = expf(v[k]-m); sum += v[k]; }
        float inv = 1.0f/sum;
        #pragma unroll
        for (int k = 0; k < NC; k++) ssm[t*NC+k] = v[k]*inv;
    }
    __syncthreads();

    for (int idx = t; idx < NC*FH; idx += 512){
        int c = idx >> 7, f = idx & 127;
        float acc = 0.0f;
        #pragma unroll 4
        for (int n = 0; n < NP; n++) acc += ssm[n*NC+c] * Hs[n*FH + f];
        xp[c*FH + f] = acc;
    }
    __syncthreads();

    if (t < 128){
        int c = t >> 4, j = t & 15;
        float m = xp[c*FH + j*8];
        #pragma unroll
        for (int u = 1; u < 8; u++) m = fmaxf(m, xp[c*FH + j*8 + u]);
        red[t] = m * fcw[t];
    }
    __syncthreads();
    if (t < 64) red[t] += red[t+64];
    __syncthreads();
    if (t < 32){
        float v = red[t] + red[t+32];
        #pragma unroll
        for (int o = 16; o; o >>= 1) v += __shfl_down_sync(0xffffffffu, v, o);
        if (t == 0) out[g] = v + fcb[0];
    }
}

// ---------------- launch ----------------
extern "C" void kernel_launch(void* const* d_in, const int* in_sizes, int n_in,
                              void* d_out, int out_size){
    const float* x    = (const float*)d_in[0];
    const int*   ei   = (const int*)  d_in[1];
    // d_in[2] = adj : unused (pool losses are discarded in reference)
    const float* s_in = (const float*)d_in[3];
    const float* Wro1 = (const float*)d_in[4];
    const float* Wre1 = (const float*)d_in[5];
    const float* b1   = (const float*)d_in[6];
    const float* Wro2 = (const float*)d_in[7];
    const float* Wre2 = (const float*)d_in[8];
    const float* b2   = (const float*)d_in[9];
    const float* Wro3 = (const float*)d_in[10];
    const float* Wre3 = (const float*)d_in[11];
    const float* b3   = (const float*)d_in[12];
    const float* fcw  = (const float*)d_in[13];
    const float* fcb  = (const float*)d_in[14];
    float* out = (float*)d_out;
    (void)in_sizes; (void)n_in; (void)out_size;

    k_init<<<(NN+255)/256, 256>>>(ei);
    k_count<<<EE/256, 256>>>(ei);
    k_offs<<<BB/8, 256>>>();
    k_scatter<<<EE/256, 256>>>(ei);
    k_sortsrc<<<(NN+255)/256, 256>>>();
    k_prepW<<<128, 256>>>(Wre2, Wro2, Wre3, Wro3);

    k_layer1<<<BB, 256>>>(x, Wre1, Wro1, b1);                 // -> g_HA

    k_gemm0<<<544, 128>>>(2, b2);                             // g_HA -> g_P, g_Rb
    k_conv<<<BB, 544>>>(2);                                   // -> g_HB

    k_gemm0<<<544, 128>>>(3, b3);                             // g_HB -> g_P, g_Rb
    k_conv<<<BB, 544>>>(3);                                   // -> g_HA

    k_pool<<<BB, 512>>>(s_in, fcw, fcb, out);
}

// round 14
// speedup vs baseline: 1.1463x; 1.1463x over previous
#include <cuda_runtime.h>
#include <math.h>

// ---------------- problem constants ----------------
#define BB   2048          // graphs
#define NP   68            // nodes per graph
#define NC   8             // clusters
#define FH   128           // hidden
#define NN   (BB*NP)       // 139264 nodes
#define EE   (BB*NP*8)     // 1114112 edges
#define EPG  (NP*8)        // 544 edges per graph
#define GT2  (NN/64)       // 2176 M-tiles of 64 rows

typedef unsigned long long ull;

// ---------------- scratch (device globals: no allocation allowed) ----------------
__device__ float g_P [(size_t)NN*FH];   // H @ W_rel
__device__ float g_Rb[(size_t)NN*FH];   // H @ W_root + b
__device__ float g_HA[(size_t)NN*FH];
__device__ float g_HB[(size_t)NN*FH];
__device__ int   g_is64;
// CSR: per-node in-edge lists (local src ids)
__device__ int           g_cnt[NN];
__device__ int           g_off[NN];
__device__ int           g_cur[NN];
__device__ unsigned char g_srcs[EE];
// k-pair-major packed weights: [layer][kp*256 + f] = (W[2kp][f], W[2kp+1][f]),
// f<128 -> Wrel, f>=128 -> Wroot
__device__ float2 g_WP[2][64*256];

// ---------------- f32x2 packed helpers ----------------
__device__ __forceinline__ void fma2(ull& d, ull a, ull b){
    asm("fma.rn.f32x2 %0, %1, %2, %0;" : "+l"(d) : "l"(a), "l"(b));
}
__device__ __forceinline__ ull dup2(float x){
    ull r; asm("mov.b64 %0, {%1, %1};" : "=l"(r) : "f"(x)); return r;
}
__device__ __forceinline__ float2 unpack2(ull v){
    float2 f; asm("mov.b64 {%0, %1}, %2;" : "=f"(f.x), "=f"(f.y) : "l"(v)); return f;
}

// ---------------- init: zero counts + edge dtype detect (int64 high words zero) ----------------
__global__ void k_init(const int* __restrict__ ei){
    int i = blockIdx.x*blockDim.x + threadIdx.x;
    if (i < NN) g_cnt[i] = 0;
    if (blockIdx.x == 0){
        __shared__ int anynz;
        if (threadIdx.x == 0) anynz = 0;
        __syncthreads();
        if (ei[2*threadIdx.x + 1] != 0) atomicOr(&anynz, 1);
        __syncthreads();
        if (threadIdx.x == 0) g_is64 = (anynz == 0) ? 1 : 0;
    }
}

__global__ void k_count(const int* __restrict__ ei){
    const int is64 = g_is64;
    int e = blockIdx.x*blockDim.x + threadIdx.x;
    if (e >= EE) return;
    int d = is64 ? ei[2*(EE + e)] : ei[EE + e];
    atomicAdd(&g_cnt[d], 1);
}

// exclusive scan per graph via warp shfl-scan (1 warp = 1 graph)
__global__ void k_offs(){
    const int g = blockIdx.x*8 + (threadIdx.x >> 5);
    const int lane = threadIdx.x & 31;
    if (g >= BB) return;
    const int base = g * EPG;
    int carry = 0;
    #pragma unroll
    for (int ch = 0; ch < 3; ch++){
        int n = ch*32 + lane;
        int valid = (n < NP);
        int v0 = valid ? g_cnt[g*NP + n] : 0;
        int v = v0;
        #pragma unroll
        for (int o = 1; o < 32; o <<= 1){
            int x = __shfl_up_sync(0xffffffffu, v, o);
            if (lane >= o) v += x;
        }
        if (valid){
            int off = base + carry + v - v0;
            g_off[g*NP + n] = off;
            g_cur[g*NP + n] = off;
        }
        carry += __shfl_sync(0xffffffffu, v, 31);
    }
}

__global__ void k_scatter(const int* __restrict__ ei){
    const int is64 = g_is64;
    int e = blockIdx.x*blockDim.x + threadIdx.x;
    if (e >= EE) return;
    int s, d;
    if (is64){ s = ei[2*e]; d = ei[2*(EE + e)]; }
    else     { s = ei[e];   d = ei[EE + e];    }
    int gs = s / NP;  int ls = s - gs*NP;
    int pos = atomicAdd(&g_cur[d], 1);
    g_srcs[pos] = (unsigned char)ls;
}

// deterministic order: insertion-sort each node's src list
__global__ void k_sortsrc(){
    int n = blockIdx.x*blockDim.x + threadIdx.x;
    if (n >= NN) return;
    int off = g_off[n], c = g_cnt[n];
    for (int i = 1; i < c; i++){
        unsigned char key = g_srcs[off+i];
        int j = i - 1;
        while (j >= 0 && g_srcs[off+j] > key){ g_srcs[off+j+1] = g_srcs[off+j]; j--; }
        g_srcs[off+j+1] = key;
    }
}

// ---------------- W prep: k-pair-major packing ----------------
__global__ void k_prepW(const float* __restrict__ Wre2, const float* __restrict__ Wro2,
                        const float* __restrict__ Wre3, const float* __restrict__ Wro3){
    int idx = blockIdx.x*blockDim.x + threadIdx.x;   // 0 .. 32767
    int layer = idx >> 14;
    int r = idx & 16383;
    int kp = r >> 8, f = r & 255;
    const float* Wrel  = layer ? Wre3 : Wre2;
    const float* Wroot = layer ? Wro3 : Wro2;
    int k = kp*2;
    float v0, v1;
    if (f < 128){ v0 = Wrel[k*128 + f];        v1 = Wrel[(k+1)*128 + f]; }
    else        { v0 = Wroot[k*128 + (f-128)]; v1 = Wroot[(k+1)*128 + (f-128)]; }
    g_WP[layer][r] = make_float2(v0, v1);
}

// ---------------- layer 1 (F_IN = 2): HA = relu(agg@Wrel + x@Wroot + b) ----------------
__global__ void k_layer1(const float* __restrict__ x,
                         const float* __restrict__ Wrel, const float* __restrict__ Wroot,
                         const float* __restrict__ b){
    __shared__ float xs[NP*2], ax[NP*2], wr[2*FH], wo[2*FH], bs[FH];
    const int g = blockIdx.x, t = threadIdx.x;
    if (t < NP*2) xs[t] = x[(size_t)g*NP*2 + t];
    if (t < FH){
        wr[t] = Wrel[t];  wr[FH+t] = Wrel[FH+t];
        wo[t] = Wroot[t]; wo[FH+t] = Wroot[FH+t];
        bs[t] = b[t];
    }
    __syncthreads();
    if (t < NP*2){
        int n = t >> 1, d = t & 1;
        int off = g_off[g*NP + n], cnt = g_cnt[g*NP + n];
        float sv = 0.0f;
        for (int i = 0; i < cnt; i++) sv += xs[((int)g_srcs[off+i])*2 + d];
        ax[t] = sv;
    }
    __syncthreads();
    for (int idx = t; idx < NP*FH; idx += blockDim.x){
        int n = idx >> 7, f = idx & 127;
        float v = ax[n*2]*wr[f] + ax[n*2+1]*wr[FH+f]
                + xs[n*2]*wo[f] + xs[n*2+1]*wo[FH+f] + bs[f];
        g_HA[(size_t)g*NP*FH + idx] = fmaxf(v, 0.0f);
    }
}

// ---------------- half-split smem dual GEMM (2 CTAs/SM) ----------------
// CTA owns one 128-col output half (half 0 -> g_P, half 1 -> g_Rb + bias).
// smem: W half as k-pair float2 image (64KB, conflict-free LDS.64) + A tile 64x128
// (pad 132, 33.8KB) + bias  => ~99.8KB  => 2 CTAs/SM, 4 warps/SMSP.
#define FST 132
#define GEMM_SMEM ((16384 + 64*FST + 128)*4)

__global__ void __launch_bounds__(256, 2) k_gemm(int layer, const float* __restrict__ bias){
    extern __shared__ float sm[];
    float2* WPs = (float2*)sm;              // 8192 float2
    float*  As  = sm + 16384;               // 64 x FST
    float*  bs  = As + 64*FST;              // 128
    const float* __restrict__ Hin = (layer == 2) ? g_HA : g_HB;
    const int t = threadIdx.x;
    const int half = blockIdx.x & 1;
    const int nstr = gridDim.x >> 1;
    const float2* __restrict__ WPg = g_WP[layer-2];

    // stage W half: WPs[kp*128 + f] = g_WP[kp*256 + half*128 + f]
    for (int i = t; i < 8192; i += 256){
        int kp = i >> 7, f = i & 127;
        WPs[i] = WPg[kp*256 + half*128 + f];
    }
    if (t < 128) bs[t] = bias[t];
    __syncthreads();

    const int w = t >> 5, c = t & 31;
    float* __restrict__ Out = half ? g_Rb : g_P;
    float bv[4];
    #pragma unroll
    for (int j = 0; j < 4; j++) bv[j] = half ? bs[c + 32*j] : 0.0f;

    for (int tile = blockIdx.x >> 1; tile < GT2; tile += nstr){
        // ---- load A tile 64x128, pad-132 smem, coalesced float4 ----
        #pragma unroll
        for (int i = 0; i < 8; i++){
            int lin = t + 256*i;            // 0..2047
            int row = lin >> 5;
            int kc  = (lin & 31) << 2;
            float4 v = *(const float4*)(Hin + (size_t)(tile*64 + row)*128 + kc);
            *(float4*)(As + row*FST + kc) = v;
        }
        __syncthreads();

        ull acc[8][4];
        #pragma unroll
        for (int i = 0; i < 8; i++)
            #pragma unroll
            for (int j = 0; j < 4; j++) acc[i][j] = 0ULL;

        const float* ar = As + (w*8)*FST;
        #pragma unroll 4
        for (int kp = 0; kp < 64; kp++){
            ull a[8], b[4];
            #pragma unroll
            for (int j = 0; j < 4; j++)
                b[j] = *(const ull*)(WPs + kp*128 + c + 32*j);
            #pragma unroll
            for (int i = 0; i < 8; i++)
                a[i] = *(const ull*)(ar + i*FST + 2*kp);
            #pragma unroll
            for (int i = 0; i < 8; i++)
                #pragma unroll
                for (int j = 0; j < 4; j++)
                    fma2(acc[i][j], a[i], b[j]);
        }

        #pragma unroll
        for (int i = 0; i < 8; i++){
            float* dst = Out + ((size_t)tile*64 + w*8 + i)*128 + c;
            #pragma unroll
            for (int j = 0; j < 4; j++){
                float2 p = unpack2(acc[i][j]);
                dst[32*j] = p.x + p.y + bv[j];
            }
        }
        __syncthreads();
    }
}

// ---------------- conv-apply (sparse): H_out = relu(sum_{j->n} P_j + Rb_n) ----------------
#define PST 130
__global__ void __launch_bounds__(544) k_conv(int layer){
    __shared__ float Ps[NP*PST];
    const int g = blockIdx.x, t = threadIdx.x;
    float* __restrict__ Hout = (layer == 2) ? g_HB : g_HA;

    const float* Pg = g_P + (size_t)g*NP*FH;
    for (int i = t; i < NP*FH; i += 544){
        int row = i >> 7, col = i & 127;
        Ps[row*PST + col] = Pg[i];
    }
    __syncthreads();

    const int n  = t >> 3;     // 0..67
    const int cg = t & 7;      // 0..7 -> pair cols cg + 8u
    const int off = g_off[g*NP + n];
    const int cnt = g_cnt[g*NP + n];

    const float* rb = g_Rb + ((size_t)g*NP + n)*FH;
    ull acc[8];
    #pragma unroll
    for (int u = 0; u < 8; u++) acc[u] = *(const ull*)(rb + 2*(cg + 8*u));

    const ull one = dup2(1.0f);
    for (int e = 0; e < cnt; e++){
        const float* pr = Ps + ((int)g_srcs[off+e])*PST;
        #pragma unroll
        for (int u = 0; u < 8; u++){
            ull pv = *(const ull*)(pr + 2*(cg + 8*u));
            fma2(acc[u], one, pv);
        }
    }
    float* ho = Hout + ((size_t)g*NP + n)*FH;
    #pragma unroll
    for (int u = 0; u < 8; u++){
        float2 v = unpack2(acc[u]);
        v.x = fmaxf(v.x, 0.0f); v.y = fmaxf(v.y, 0.0f);
        *(float2*)(ho + 2*(cg + 8*u)) = v;
    }
}

// ---------------- pool: softmax(s) einsum, maxpool(1,8), fc ----------------
__global__ void __launch_bounds__(512) k_pool(const float* __restrict__ s_in,
                       const float* __restrict__ fcw, const float* __restrict__ fcb,
                       float* __restrict__ out){
    __shared__ float Hs[NP*FH];
    __shared__ float ssm[NP*NC];
    __shared__ float xp[NC*FH];
    __shared__ float red[128];
    const int g = blockIdx.x, t = threadIdx.x;

    const float* Hg = g_HA + (size_t)g*NP*FH;
    for (int i = t; i < NP*FH; i += 512) Hs[i] = Hg[i];

    if (t < NP){
        float v[NC]; float m = -1e30f;
        #pragma unroll
        for (int k = 0; k < NC; k++){ v[k] = s_in[((size_t)g*NP + t)*NC + k]; m = fmaxf(m, v[k]); }
        float sum = 0.0f;
        #pragma unroll
        for (int k = 0; k < NC; k++){ v[k] = expf(v[k]-m); sum += v[k]; }
        float inv = 1.0f/sum;
        #pragma unroll
        for (int k = 0; k < NC; k++) ssm[t*NC+k] = v[k]*inv;
    }
    __syncthreads();

    for (int idx = t; idx < NC*FH; idx += 512){
        int c = idx >> 7, f = idx & 127;
        float acc = 0.0f;
        #pragma unroll 4
        for (int n = 0; n < NP; n++) acc += ssm[n*NC+c] * Hs[n*FH + f];
        xp[c*FH + f] = acc;
    }
    __syncthreads();

    if (t < 128){
        int c = t >> 4, j = t & 15;
        float m = xp[c*FH + j*8];
        #pragma unroll
        for (int u = 1; u < 8; u++) m = fmaxf(m, xp[c*FH + j*8 + u]);
        red[t] = m * fcw[t];
    }
    __syncthreads();
    if (t < 64) red[t] += red[t+64];
    __syncthreads();
    if (t < 32){
        float v = red[t] + red[t+32];
        #pragma unroll
        for (int o = 16; o; o >>= 1) v += __shfl_down_sync(0xffffffffu, v, o);
        if (t == 0) out[g] = v + fcb[0];
    }
}

// ---------------- launch ----------------
extern "C" void kernel_launch(void* const* d_in, const int* in_sizes, int n_in,
                              void* d_out, int out_size){
    const float* x    = (const float*)d_in[0];
    const int*   ei   = (const int*)  d_in[1];
    // d_in[2] = adj : unused (pool losses are discarded in reference)
    const float* s_in = (const float*)d_in[3];
    const float* Wro1 = (const float*)d_in[4];
    const float* Wre1 = (const float*)d_in[5];
    const float* b1   = (const float*)d_in[6];
    const float* Wro2 = (const float*)d_in[7];
    const float* Wre2 = (const float*)d_in[8];
    const float* b2   = (const float*)d_in[9];
    const float* Wro3 = (const float*)d_in[10];
    const float* Wre3 = (const float*)d_in[11];
    const float* b3   = (const float*)d_in[12];
    const float* fcw  = (const float*)d_in[13];
    const float* fcb  = (const float*)d_in[14];
    float* out = (float*)d_out;
    (void)in_sizes; (void)n_in; (void)out_size;

    cudaFuncSetAttribute(k_gemm, cudaFuncAttributeMaxDynamicSharedMemorySize, GEMM_SMEM);

    k_init<<<(NN+255)/256, 256>>>(ei);
    k_count<<<EE/256, 256>>>(ei);
    k_offs<<<BB/8, 256>>>();
    k_scatter<<<EE/256, 256>>>(ei);
    k_sortsrc<<<(NN+255)/256, 256>>>();
    k_prepW<<<128, 256>>>(Wre2, Wro2, Wre3, Wro3);

    k_layer1<<<BB, 256>>>(x, Wre1, Wro1, b1);                 // -> g_HA

    k_gemm<<<592, 256, GEMM_SMEM>>>(2, b2);                   // g_HA -> g_P, g_Rb
    k_conv<<<BB, 544>>>(2);                                   // -> g_HB

    k_gemm<<<592, 256, GEMM_SMEM>>>(3, b3);                   // g_HB -> g_P, g_Rb
    k_conv<<<BB, 544>>>(3);                                   // -> g_HA

    k_pool<<<BB, 512>>>(s_in, fcw, fcb, out);
}

// round 15
// speedup vs baseline: 1.1643x; 1.0157x over previous
#include <cuda_runtime.h>
#include <math.h>

// ---------------- problem constants ----------------
#define BB   2048          // graphs
#define NP   68            // nodes per graph
#define NC   8             // clusters
#define FH   128           // hidden
#define NN   (BB*NP)       // 139264 nodes
#define EE   (BB*NP*8)     // 1114112 edges
#define EPG  (NP*8)        // 544 edges per graph
#define GT2  (NN/64)       // 2176 M-tiles of 64 rows

typedef unsigned long long ull;
typedef unsigned int uint32;

// ---------------- scratch (device globals: no allocation allowed) ----------------
__device__ float g_P [(size_t)NN*FH];   // H @ W_rel
__device__ float g_Rb[(size_t)NN*FH];   // H @ W_root + b
__device__ float g_HA[(size_t)NN*FH];
__device__ float g_HB[(size_t)NN*FH];
// CSR: per-node in-edge lists (local src ids)
__device__ int           g_cnt[NN];
__device__ int           g_off[NN];
__device__ unsigned char g_srcs[EE];
// k-quad-major packed weights: [layer][kq*256 + f] = (W[4kq..4kq+3][f]),
// f<128 -> Wrel, f>=128 -> Wroot
__device__ float4 g_WQ[2][32*256];

// ---------------- f32x2 packed helpers ----------------
__device__ __forceinline__ void fma2(ull& d, ull a, ull b){
    asm("fma.rn.f32x2 %0, %1, %2, %0;" : "+l"(d) : "l"(a), "l"(b));
}
__device__ __forceinline__ ull pack2(uint32 lo, uint32 hi){
    ull r; asm("mov.b64 %0, {%1, %2};" : "=l"(r) : "r"(lo), "r"(hi)); return r;
}
__device__ __forceinline__ ull dup2(float x){
    ull r; asm("mov.b64 %0, {%1, %1};" : "=l"(r) : "f"(x)); return r;
}
__device__ __forceinline__ float2 unpack2(ull v){
    float2 f; asm("mov.b64 {%0, %1}, %2;" : "=f"(f.x), "=f"(f.y) : "l"(v)); return f;
}

// ---------------- single-kernel CSR build: one block per graph ----------------
// Graph g's edges are contiguous: [g*EPG, (g+1)*EPG). Detect int64-vs-int32 per
// block from its own slice (int64 high words are all zero; impossible for int32
// random edge values), histogram + warp-scan + scatter + per-node insertion sort
// all in smem, then one coalesced write-out.
__global__ void __launch_bounds__(EPG) k_csr(const int* __restrict__ ei){
    __shared__ int cnt[NP], off[NP], cur[NP];
    __shared__ unsigned char srcs[EPG];
    __shared__ int anynz;
    const int g = blockIdx.x, t = threadIdx.x;
    if (t == 0) anynz = 0;
    if (t < NP) cnt[t] = 0;
    __syncthreads();

    const size_t e = (size_t)g*EPG + t;
    if (ei[2*e + 1] != 0) atomicOr(&anynz, 1);
    __syncthreads();
    const int is64 = (anynz == 0);

    int s, d;
    if (is64){ s = ei[2*e]; d = ei[2*(EE + e)]; }
    else     { s = ei[e];   d = ei[EE + e];    }
    const int ls = s % NP;
    const int ld = d % NP;
    atomicAdd(&cnt[ld], 1);
    __syncthreads();

    if (t < 32){
        int carry = 0;
        #pragma unroll
        for (int ch = 0; ch < 3; ch++){
            int n = ch*32 + t;
            int valid = (n < NP);
            int v0 = valid ? cnt[n] : 0;
            int v = v0;
            #pragma unroll
            for (int o = 1; o < 32; o <<= 1){
                int x = __shfl_up_sync(0xffffffffu, v, o);
                if (t >= o) v += x;
            }
            if (valid){ off[n] = carry + v - v0; cur[n] = off[n]; }
            carry += __shfl_sync(0xffffffffu, v, 31);
        }
    }
    __syncthreads();

    int pos = atomicAdd(&cur[ld], 1);
    srcs[pos] = (unsigned char)ls;
    __syncthreads();

    // deterministic order: insertion-sort each node's src list
    if (t < NP){
        int o = off[t], c = cnt[t];
        for (int i = 1; i < c; i++){
            unsigned char key = srcs[o+i];
            int j = i - 1;
            while (j >= 0 && srcs[o+j] > key){ srcs[o+j+1] = srcs[o+j]; j--; }
            srcs[o+j+1] = key;
        }
    }
    __syncthreads();

    g_srcs[(size_t)g*EPG + t] = srcs[t];
    if (t < NP){
        g_off[g*NP + t] = g*EPG + off[t];
        g_cnt[g*NP + t] = cnt[t];
    }
}

// ---------------- W prep: k-quad-major packing ----------------
__global__ void k_prepW(const float* __restrict__ Wre2, const float* __restrict__ Wro2,
                        const float* __restrict__ Wre3, const float* __restrict__ Wro3){
    int idx = blockIdx.x*blockDim.x + threadIdx.x;   // 0 .. 16383
    int layer = idx >> 13;
    int r = idx & 8191;
    int kq = r >> 8, f = r & 255;
    const float* Wrel  = layer ? Wre3 : Wre2;
    const float* Wroot = layer ? Wro3 : Wro2;
    const float* W = (f < 128) ? Wrel : Wroot;
    int ff = f & 127;
    int k = kq*4;
    float4 v;
    v.x = W[(k+0)*128 + ff];
    v.y = W[(k+1)*128 + ff];
    v.z = W[(k+2)*128 + ff];
    v.w = W[(k+3)*128 + ff];
    g_WQ[layer][r] = v;
}

// ---------------- layer 1 (F_IN = 2): HA = relu(agg@Wrel + x@Wroot + b) ----------------
__global__ void k_layer1(const float* __restrict__ x,
                         const float* __restrict__ Wrel, const float* __restrict__ Wroot,
                         const float* __restrict__ b){
    __shared__ float xs[NP*2], ax[NP*2], wr[2*FH], wo[2*FH], bs[FH];
    const int g = blockIdx.x, t = threadIdx.x;
    if (t < NP*2) xs[t] = x[(size_t)g*NP*2 + t];
    if (t < FH){
        wr[t] = Wrel[t];  wr[FH+t] = Wrel[FH+t];
        wo[t] = Wroot[t]; wo[FH+t] = Wroot[FH+t];
        bs[t] = b[t];
    }
    __syncthreads();
    if (t < NP*2){
        int n = t >> 1, d = t & 1;
        int off = g_off[g*NP + n], cnt = g_cnt[g*NP + n];
        float sv = 0.0f;
        for (int i = 0; i < cnt; i++) sv += xs[((int)g_srcs[off+i])*2 + d];
        ax[t] = sv;
    }
    __syncthreads();
    for (int idx = t; idx < NP*FH; idx += blockDim.x){
        int n = idx >> 7, f = idx & 127;
        float v = ax[n*2]*wr[f] + ax[n*2+1]*wr[FH+f]
                + xs[n*2]*wo[f] + xs[n*2+1]*wo[FH+f] + bs[f];
        g_HA[(size_t)g*NP*FH + idx] = fmaxf(v, 0.0f);
    }
}

// ---------------- half-split smem dual GEMM, k-quad LDS.128 (2 CTAs/SM) ----------------
// CTA owns one 128-col output half (half 0 -> g_P, half 1 -> g_Rb + bias).
// smem: W half as k-quad float4 image (64KB) + A tile 64x128 (pad 132) + bias.
// Per 4-k iter per warp: 8 broadcast A-LDS.128 + 4 B-LDS.128 = 24 crossbar cycles
// vs 128 fma cycles -> fma-bound with 25% crossbar slack.
#define FST 132
#define GEMM_SMEM ((16384 + 64*FST + 128)*4)

__global__ void __launch_bounds__(256, 2) k_gemm(int layer, const float* __restrict__ bias){
    extern __shared__ float sm[];
    float4* WQs = (float4*)sm;              // 4096 float4 = 64KB
    float*  As  = sm + 16384;               // 64 x FST
    float*  bs  = As + 64*FST;              // 128
    const float* __restrict__ Hin = (layer == 2) ? g_HA : g_HB;
    const int t = threadIdx.x;
    const int half = blockIdx.x & 1;
    const int nstr = gridDim.x >> 1;
    const float4* __restrict__ WQg = g_WQ[layer-2];

    // stage W half: WQs[kq*128 + f] = g_WQ[kq*256 + half*128 + f]
    for (int i = t; i < 4096; i += 256){
        int kq = i >> 7, f = i & 127;
        WQs[i] = WQg[kq*256 + half*128 + f];
    }
    if (t < 128) bs[t] = bias[t];
    __syncthreads();

    const int w = t >> 5, c = t & 31;
    float* __restrict__ Out = half ? g_Rb : g_P;
    float bv[4];
    #pragma unroll
    for (int j = 0; j < 4; j++) bv[j] = half ? bs[c + 32*j] : 0.0f;

    for (int tile = blockIdx.x >> 1; tile < GT2; tile += nstr){
        // ---- load A tile 64x128, pad-132 smem, coalesced float4 ----
        #pragma unroll
        for (int i = 0; i < 8; i++){
            int lin = t + 256*i;            // 0..2047
            int row = lin >> 5;
            int kc  = (lin & 31) << 2;
            float4 v = *(const float4*)(Hin + (size_t)(tile*64 + row)*128 + kc);
            *(float4*)(As + row*FST + kc) = v;
        }
        __syncthreads();

        ull acc[8][4];
        #pragma unroll
        for (int i = 0; i < 8; i++)
            #pragma unroll
            for (int j = 0; j < 4; j++) acc[i][j] = 0ULL;

        const float* ar = As + (w*8)*FST;
        #pragma unroll 2
        for (int kq = 0; kq < 32; kq++){
            ull b01[4], b23[4];
            #pragma unroll
            for (int j = 0; j < 4; j++){
                uint4 bq = *(const uint4*)(WQs + kq*128 + c + 32*j);
                b01[j] = pack2(bq.x, bq.y);
                b23[j] = pack2(bq.z, bq.w);
            }
            #pragma unroll
            for (int i = 0; i < 8; i++){
                uint4 aq = *(const uint4*)(ar + i*FST + 4*kq);
                ull a01 = pack2(aq.x, aq.y);
                ull a23 = pack2(aq.z, aq.w);
                #pragma unroll
                for (int j = 0; j < 4; j++){
                    fma2(acc[i][j], a01, b01[j]);
                    fma2(acc[i][j], a23, b23[j]);
                }
            }
        }

        #pragma unroll
        for (int i = 0; i < 8; i++){
            float* dst = Out + ((size_t)tile*64 + w*8 + i)*128 + c;
            #pragma unroll
            for (int j = 0; j < 4; j++){
                float2 p = unpack2(acc[i][j]);
                dst[32*j] = p.x + p.y + bv[j];
            }
        }
        __syncthreads();
    }
}

// ---------------- conv-apply (sparse): H_out = relu(sum_{j->n} P_j + Rb_n) ----------------
#define PST 130
__global__ void __launch_bounds__(544) k_conv(int layer){
    __shared__ float Ps[NP*PST];
    const int g = blockIdx.x, t = threadIdx.x;
    float* __restrict__ Hout = (layer == 2) ? g_HB : g_HA;

    const float* Pg = g_P + (size_t)g*NP*FH;
    for (int i = t; i < NP*FH; i += 544){
        int row = i >> 7, col = i & 127;
        Ps[row*PST + col] = Pg[i];
    }
    __syncthreads();

    const int n  = t >> 3;     // 0..67
    const int cg = t & 7;      // 0..7 -> pair cols cg + 8u
    const int off = g_off[g*NP + n];
    const int cnt = g_cnt[g*NP + n];

    const float* rb = g_Rb + ((size_t)g*NP + n)*FH;
    ull acc[8];
    #pragma unroll
    for (int u = 0; u < 8; u++) acc[u] = *(const ull*)(rb + 2*(cg + 8*u));

    const ull one = dup2(1.0f);
    for (int e = 0; e < cnt; e++){
        const float* pr = Ps + ((int)g_srcs[off+e])*PST;
        #pragma unroll
        for (int u = 0; u < 8; u++){
            ull pv = *(const ull*)(pr + 2*(cg + 8*u));
            fma2(acc[u], one, pv);
        }
    }
    float* ho = Hout + ((size_t)g*NP + n)*FH;
    #pragma unroll
    for (int u = 0; u < 8; u++){
        float2 v = unpack2(acc[u]);
        v.x = fmaxf(v.x, 0.0f); v.y = fmaxf(v.y, 0.0f);
        *(float2*)(ho + 2*(cg + 8*u)) = v;
    }
}

// ---------------- pool: softmax(s) einsum, maxpool(1,8), fc ----------------
__global__ void __launch_bounds__(512) k_pool(const float* __restrict__ s_in,
                       const float* __restrict__ fcw, const float* __restrict__ fcb,
                       float* __restrict__ out){
    __shared__ float Hs[NP*FH];
    __shared__ float ssm[NP*NC];
    __shared__ float xp[NC*FH];
    __shared__ float red[128];
    const int g = blockIdx.x, t = threadIdx.x;

    const float* Hg = g_HA + (size_t)g*NP*FH;
    for (int i = t; i < NP*FH; i += 512) Hs[i] = Hg[i];

    if (t < NP){
        float v[NC]; float m = -1e30f;
        #pragma unroll
        for (int k = 0; k < NC; k++){ v[k] = s_in[((size_t)g*NP + t)*NC + k]; m = fmaxf(m, v[k]); }
        float sum = 0.0f;
        #pragma unroll
        for (int k = 0; k < NC; k++){ v[k] = expf(v[k]-m); sum += v[k]; }
        float inv = 1.0f/sum;
        #pragma unroll
        for (int k = 0; k < NC; k++) ssm[t*NC+k] = v[k]*inv;
    }
    __syncthreads();

    for (int idx = t; idx < NC*FH; idx += 512){
        int c = idx >> 7, f = idx & 127;
        float acc = 0.0f;
        #pragma unroll 4
        for (int n = 0; n < NP; n++) acc += ssm[n*NC+c] * Hs[n*FH + f];
        xp[c*FH + f] = acc;
    }
    __syncthreads();

    if (t < 128){
        int c = t >> 4, j = t & 15;
        float m = xp[c*FH + j*8];
        #pragma unroll
        for (int u = 1; u < 8; u++) m = fmaxf(m, xp[c*FH + j*8 + u]);
        red[t] = m * fcw[t];
    }
    __syncthreads();
    if (t < 64) red[t] += red[t+64];
    __syncthreads();
    if (t < 32){
        float v = red[t] + red[t+32];
        #pragma unroll
        for (int o = 16; o; o >>= 1) v += __shfl_down_sync(0xffffffffu, v, o);
        if (t == 0) out[g] = v + fcb[0];
    }
}

// ---------------- launch ----------------
extern "C" void kernel_launch(void* const* d_in, const int* in_sizes, int n_in,
                              void* d_out, int out_size){
    const float* x    = (const float*)d_in[0];
    const int*   ei   = (const int*)  d_in[1];
    // d_in[2] = adj : unused (pool losses are discarded in reference)
    const float* s_in = (const float*)d_in[3];
    const float* Wro1 = (const float*)d_in[4];
    const float* Wre1 = (const float*)d_in[5];
    const float* b1   = (const float*)d_in[6];
    const float* Wro2 = (const float*)d_in[7];
    const float* Wre2 = (const float*)d_in[8];
    const float* b2   = (const float*)d_in[9];
    const float* Wro3 = (const float*)d_in[10];
    const float* Wre3 = (const float*)d_in[11];
    const float* b3   = (const float*)d_in[12];
    const float* fcw  = (const float*)d_in[13];
    const float* fcb  = (const float*)d_in[14];
    float* out = (float*)d_out;
    (void)in_sizes; (void)n_in; (void)out_size;

    cudaFuncSetAttribute(k_gemm, cudaFuncAttributeMaxDynamicSharedMemorySize, GEMM_SMEM);

    k_csr<<<BB, EPG>>>(ei);
    k_prepW<<<64, 256>>>(Wre2, Wro2, Wre3, Wro3);

    k_layer1<<<BB, 256>>>(x, Wre1, Wro1, b1);                 // -> g_HA

    k_gemm<<<592, 256, GEMM_SMEM>>>(2, b2);                   // g_HA -> g_P, g_Rb
    k_conv<<<BB, 544>>>(2);                                   // -> g_HB

    k_gemm<<<592, 256, GEMM_SMEM>>>(3, b3);                   // g_HB -> g_P, g_Rb
    k_conv<<<BB, 544>>>(3);                                   // -> g_HA

    k_pool<<<BB, 512>>>(s_in, fcw, fcb, out);
}

// round 16
// speedup vs baseline: 1.1675x; 1.0027x over previous
#include <cuda_runtime.h>
#include <math.h>

// ---------------- problem constants ----------------
#define BB   2048          // graphs
#define NP   68            // nodes per graph
#define NC   8             // clusters
#define FH   128           // hidden
#define NN   (BB*NP)       // 139264 nodes
#define EE   (BB*NP*8)     // 1114112 edges
#define EPG  (NP*8)        // 544 edges per graph
#define GT32 (NN/32)       // 4352 M-tiles of 32 rows

typedef unsigned long long ull;
typedef unsigned int uint32;

// ---------------- scratch (device globals: no allocation allowed) ----------------
__device__ float g_P [(size_t)NN*FH];   // H @ W_rel
__device__ float g_Rb[(size_t)NN*FH];   // H @ W_root + b
__device__ float g_HA[(size_t)NN*FH];
__device__ float g_HB[(size_t)NN*FH];
// CSR: per-node in-edge lists (local src ids)
__device__ int           g_cnt[NN];
__device__ int           g_off[NN];
__device__ unsigned char g_srcs[EE];
// k-quad-major packed weights: [layer][kq*256 + f] = (W[4kq..4kq+3][f]),
// f<128 -> Wrel, f>=128 -> Wroot
__device__ float4 g_WQ[2][32*256];

// ---------------- f32x2 packed helpers ----------------
__device__ __forceinline__ void fma2(ull& d, ull a, ull b){
    asm("fma.rn.f32x2 %0, %1, %2, %0;" : "+l"(d) : "l"(a), "l"(b));
}
__device__ __forceinline__ ull pack2(uint32 lo, uint32 hi){
    ull r; asm("mov.b64 %0, {%1, %2};" : "=l"(r) : "r"(lo), "r"(hi)); return r;
}
__device__ __forceinline__ ull dup2(float x){
    ull r; asm("mov.b64 %0, {%1, %1};" : "=l"(r) : "f"(x)); return r;
}
__device__ __forceinline__ float2 unpack2(ull v){
    float2 f; asm("mov.b64 {%0, %1}, %2;" : "=f"(f.x), "=f"(f.y) : "l"(v)); return f;
}
__device__ __forceinline__ uint32 smem_u32(const void* p){
    uint32 a; asm("{ .reg .u64 t; cvta.to.shared.u64 t, %1; cvt.u32.u64 %0, t; }" : "=r"(a) : "l"(p));
    return a;
}

// ---------------- single-kernel CSR build: one block per graph ----------------
__global__ void __launch_bounds__(EPG) k_csr(const int* __restrict__ ei){
    __shared__ int cnt[NP], off[NP], cur[NP];
    __shared__ unsigned char srcs[EPG];
    __shared__ int anynz;
    const int g = blockIdx.x, t = threadIdx.x;
    if (t == 0) anynz = 0;
    if (t < NP) cnt[t] = 0;
    __syncthreads();

    const size_t e = (size_t)g*EPG + t;
    if (ei[2*e + 1] != 0) atomicOr(&anynz, 1);
    __syncthreads();
    const int is64 = (anynz == 0);

    int s, d;
    if (is64){ s = ei[2*e]; d = ei[2*(EE + e)]; }
    else     { s = ei[e];   d = ei[EE + e];    }
    const int ls = s % NP;
    const int ld = d % NP;
    atomicAdd(&cnt[ld], 1);
    __syncthreads();

    if (t < 32){
        int carry = 0;
        #pragma unroll
        for (int ch = 0; ch < 3; ch++){
            int n = ch*32 + t;
            int valid = (n < NP);
            int v0 = valid ? cnt[n] : 0;
            int v = v0;
            #pragma unroll
            for (int o = 1; o < 32; o <<= 1){
                int x = __shfl_up_sync(0xffffffffu, v, o);
                if (t >= o) v += x;
            }
            if (valid){ off[n] = carry + v - v0; cur[n] = off[n]; }
            carry += __shfl_sync(0xffffffffu, v, 31);
        }
    }
    __syncthreads();

    int pos = atomicAdd(&cur[ld], 1);
    srcs[pos] = (unsigned char)ls;
    __syncthreads();

    // deterministic order: insertion-sort each node's src list
    if (t < NP){
        int o = off[t], c = cnt[t];
        for (int i = 1; i < c; i++){
            unsigned char key = srcs[o+i];
            int j = i - 1;
            while (j >= 0 && srcs[o+j] > key){ srcs[o+j+1] = srcs[o+j]; j--; }
            srcs[o+j+1] = key;
        }
    }
    __syncthreads();

    g_srcs[(size_t)g*EPG + t] = srcs[t];
    if (t < NP){
        g_off[g*NP + t] = g*EPG + off[t];
        g_cnt[g*NP + t] = cnt[t];
    }
}

// ---------------- W prep: k-quad-major packing ----------------
__global__ void k_prepW(const float* __restrict__ Wre2, const float* __restrict__ Wro2,
                        const float* __restrict__ Wre3, const float* __restrict__ Wro3){
    int idx = blockIdx.x*blockDim.x + threadIdx.x;   // 0 .. 16383
    int layer = idx >> 13;
    int r = idx & 8191;
    int kq = r >> 8, f = r & 255;
    const float* Wrel  = layer ? Wre3 : Wre2;
    const float* Wroot = layer ? Wro3 : Wro2;
    const float* W = (f < 128) ? Wrel : Wroot;
    int ff = f & 127;
    int k = kq*4;
    float4 v;
    v.x = W[(k+0)*128 + ff];
    v.y = W[(k+1)*128 + ff];
    v.z = W[(k+2)*128 + ff];
    v.w = W[(k+3)*128 + ff];
    g_WQ[layer][r] = v;
}

// ---------------- layer 1 (F_IN = 2): HA = relu(agg@Wrel + x@Wroot + b) ----------------
__global__ void k_layer1(const float* __restrict__ x,
                         const float* __restrict__ Wrel, const float* __restrict__ Wroot,
                         const float* __restrict__ b){
    __shared__ float xs[NP*2], ax[NP*2], wr[2*FH], wo[2*FH], bs[FH];
    const int g = blockIdx.x, t = threadIdx.x;
    if (t < NP*2) xs[t] = x[(size_t)g*NP*2 + t];
    if (t < FH){
        wr[t] = Wrel[t];  wr[FH+t] = Wrel[FH+t];
        wo[t] = Wroot[t]; wo[FH+t] = Wroot[FH+t];
        bs[t] = b[t];
    }
    __syncthreads();
    if (t < NP*2){
        int n = t >> 1, d = t & 1;
        int off = g_off[g*NP + n], cnt = g_cnt[g*NP + n];
        float sv = 0.0f;
        for (int i = 0; i < cnt; i++) sv += xs[((int)g_srcs[off+i])*2 + d];
        ax[t] = sv;
    }
    __syncthreads();
    for (int idx = t; idx < NP*FH; idx += blockDim.x){
        int n = idx >> 7, f = idx & 127;
        float v = ax[n*2]*wr[f] + ax[n*2+1]*wr[FH+f]
                + xs[n*2]*wo[f] + xs[n*2+1]*wo[FH+f] + bs[f];
        g_HA[(size_t)g*NP*FH + idx] = fmaxf(v, 0.0f);
    }
}

// ---------------- cp.async double-buffered half-split dual GEMM (2 CTAs/SM) ----------------
// CTA owns one 128-col output half (half 0 -> g_P, half 1 -> g_Rb + bias).
// A tiles (32 rows x 128 k, 16KB) stream in via cp.async into a double buffer while
// the current tile is computed. Warp tile = 8 rows x 64 cols -> acc 8x2 ull = 32 regs.
// smem: W-half k-quad image 64KB + 2x16KB A + bias = 96.6KB -> 2 CTAs/SM, 16 warps.
#define GEMM_SMEM ((16384 + 4096 + 4096 + 128)*4)

__device__ __forceinline__ void cp_tile(uint32 sbase, const float* __restrict__ gbase, int t){
    #pragma unroll
    for (int i = 0; i < 4; i++){
        int idx = t + 256*i;                 // 0..1023 chunks of 16B
        uint32 saddr = sbase + idx*16;
        const float* g = gbase + idx*4;
        asm volatile("cp.async.cg.shared.global [%0], [%1], 16;"
            :: "r"(saddr), "l"(g) : "memory");
    }
}

__global__ void __launch_bounds__(256, 2) k_gemm(int layer, const float* __restrict__ bias){
    extern __shared__ float sm[];
    float4* WQs = (float4*)sm;              // 4096 float4 = 64KB
    float*  A0  = sm + 16384;               // 32x128
    float*  A1  = A0 + 4096;                // 32x128
    float*  bs  = A1 + 4096;                // 128
    const float* __restrict__ Hin = (layer == 2) ? g_HA : g_HB;
    const int t = threadIdx.x;
    const int half = blockIdx.x & 1;
    const int nstr = gridDim.x >> 1;
    const float4* __restrict__ WQg = g_WQ[layer-2];

    // stage W half: WQs[kq*128 + f] = g_WQ[kq*256 + half*128 + f]
    for (int i = t; i < 4096; i += 256){
        int kq = i >> 7, f = i & 127;
        WQs[i] = WQg[kq*256 + half*128 + f];
    }
    if (t < 128) bs[t] = bias[t];

    const uint32 a0s = smem_u32(A0), a1s = smem_u32(A1);
    const int w = t >> 5, c = t & 31;
    const int rg = w & 3, cg = w >> 2;
    float* __restrict__ Out = half ? g_Rb : g_P;

    const int tile0 = blockIdx.x >> 1;
    cp_tile(a0s, Hin + (size_t)tile0*4096, t);
    asm volatile("cp.async.commit_group;" ::: "memory");

    int cur = 0;
    for (int tile = tile0; tile < GT32; tile += nstr){
        int nxt = tile + nstr;
        if (nxt < GT32) cp_tile(cur ? a0s : a1s, Hin + (size_t)nxt*4096, t);
        asm volatile("cp.async.commit_group;" ::: "memory");
        asm volatile("cp.async.wait_group 1;" ::: "memory");
        __syncthreads();                     // current buffer (and W/bias) visible

        const float* ar = (cur ? A1 : A0) + rg*8*128;

        ull acc[8][2];
        #pragma unroll
        for (int i = 0; i < 8; i++){ acc[i][0] = 0ULL; acc[i][1] = 0ULL; }

        #pragma unroll 4
        for (int kq = 0; kq < 32; kq++){
            ull b01[2], b23[2];
            #pragma unroll
            for (int j = 0; j < 2; j++){
                uint4 bq = *(const uint4*)(WQs + kq*128 + cg*64 + c + 32*j);
                b01[j] = pack2(bq.x, bq.y);
                b23[j] = pack2(bq.z, bq.w);
            }
            #pragma unroll
            for (int i = 0; i < 8; i++){
                uint4 aq = *(const uint4*)(ar + i*128 + kq*4);   // warp-broadcast
                ull a01 = pack2(aq.x, aq.y);
                ull a23 = pack2(aq.z, aq.w);
                fma2(acc[i][0], a01, b01[0]);
                fma2(acc[i][0], a23, b23[0]);
                fma2(acc[i][1], a01, b01[1]);
                fma2(acc[i][1], a23, b23[1]);
            }
        }

        #pragma unroll
        for (int i = 0; i < 8; i++){
            size_t row = (size_t)tile*32 + rg*8 + i;
            #pragma unroll
            for (int j = 0; j < 2; j++){
                int col = cg*64 + c + 32*j;
                float2 p = unpack2(acc[i][j]);
                Out[row*128 + col] = p.x + p.y + (half ? bs[col] : 0.0f);
            }
        }
        __syncthreads();                     // all reads of buf done before refill
        cur ^= 1;
    }
}

// ---------------- conv-apply (sparse): H_out = relu(sum_{j->n} P_j + Rb_n) ----------------
#define PST 130
__global__ void __launch_bounds__(544) k_conv(int layer){
    __shared__ float Ps[NP*PST];
    const int g = blockIdx.x, t = threadIdx.x;
    float* __restrict__ Hout = (layer == 2) ? g_HB : g_HA;

    const float* Pg = g_P + (size_t)g*NP*FH;
    for (int i = t; i < NP*FH; i += 544){
        int row = i >> 7, col = i & 127;
        Ps[row*PST + col] = Pg[i];
    }
    __syncthreads();

    const int n  = t >> 3;     // 0..67
    const int cg = t & 7;      // 0..7 -> pair cols cg + 8u
    const int off = g_off[g*NP + n];
    const int cnt = g_cnt[g*NP + n];

    const float* rb = g_Rb + ((size_t)g*NP + n)*FH;
    ull acc[8];
    #pragma unroll
    for (int u = 0; u < 8; u++) acc[u] = *(const ull*)(rb + 2*(cg + 8*u));

    const ull one = dup2(1.0f);
    for (int e = 0; e < cnt; e++){
        const float* pr = Ps + ((int)g_srcs[off+e])*PST;
        #pragma unroll
        for (int u = 0; u < 8; u++){
            ull pv = *(const ull*)(pr + 2*(cg + 8*u));
            fma2(acc[u], one, pv);
        }
    }
    float* ho = Hout + ((size_t)g*NP + n)*FH;
    #pragma unroll
    for (int u = 0; u < 8; u++){
        float2 v = unpack2(acc[u]);
        v.x = fmaxf(v.x, 0.0f); v.y = fmaxf(v.y, 0.0f);
        *(float2*)(ho + 2*(cg + 8*u)) = v;
    }
}

// ---------------- pool: softmax(s) einsum, maxpool(1,8), fc ----------------
__global__ void __launch_bounds__(512) k_pool(const float* __restrict__ s_in,
                       const float* __restrict__ fcw, const float* __restrict__ fcb,
                       float* __restrict__ out){
    __shared__ float Hs[NP*FH];
    __shared__ float ssm[NP*NC];
    __shared__ float xp[NC*FH];
    __shared__ float red[128];
    const int g = blockIdx.x, t = threadIdx.x;

    const float* Hg = g_HA + (size_t)g*NP*FH;
    for (int i = t; i < NP*FH; i += 512) Hs[i] = Hg[i];

    if (t < NP){
        float v[NC]; float m = -1e30f;
        #pragma unroll
        for (int k = 0; k < NC; k++){ v[k] = s_in[((size_t)g*NP + t)*NC + k]; m = fmaxf(m, v[k]); }
        float sum = 0.0f;
        #pragma unroll
        for (int k = 0; k < NC; k++){ v[k] = expf(v[k]-m); sum += v[k]; }
        float inv = 1.0f/sum;
        #pragma unroll
        for (int k = 0; k < NC; k++) ssm[t*NC+k] = v[k]*inv;
    }
    __syncthreads();

    for (int idx = t; idx < NC*FH; idx += 512){
        int c = idx >> 7, f = idx & 127;
        float acc = 0.0f;
        #pragma unroll 4
        for (int n = 0; n < NP; n++) acc += ssm[n*NC+c] * Hs[n*FH + f];
        xp[c*FH + f] = acc;
    }
    __syncthreads();

    if (t < 128){
        int c = t >> 4, j = t & 15;
        float m = xp[c*FH + j*8];
        #pragma unroll
        for (int u = 1; u < 8; u++) m = fmaxf(m, xp[c*FH + j*8 + u]);
        red[t] = m * fcw[t];
    }
    __syncthreads();
    if (t < 64) red[t] += red[t+64];
    __syncthreads();
    if (t < 32){
        float v = red[t] + red[t+32];
        #pragma unroll
        for (int o = 16; o; o >>= 1) v += __shfl_down_sync(0xffffffffu, v, o);
        if (t == 0) out[g] = v + fcb[0];
    }
}

// ---------------- launch ----------------
extern "C" void kernel_launch(void* const* d_in, const int* in_sizes, int n_in,
                              void* d_out, int out_size){
    const float* x    = (const float*)d_in[0];
    const int*   ei   = (const int*)  d_in[1];
    // d_in[2] = adj : unused (pool losses are discarded in reference)
    const float* s_in = (const float*)d_in[3];
    const float* Wro1 = (const float*)d_in[4];
    const float* Wre1 = (const float*)d_in[5];
    const float* b1   = (const float*)d_in[6];
    const float* Wro2 = (const float*)d_in[7];
    const float* Wre2 = (const float*)d_in[8];
    const float* b2   = (const float*)d_in[9];
    const float* Wro3 = (const float*)d_in[10];
    const float* Wre3 = (const float*)d_in[11];
    const float* b3   = (const float*)d_in[12];
    const float* fcw  = (const float*)d_in[13];
    const float* fcb  = (const float*)d_in[14];
    float* out = (float*)d_out;
    (void)in_sizes; (void)n_in; (void)out_size;

    cudaFuncSetAttribute(k_gemm, cudaFuncAttributeMaxDynamicSharedMemorySize, GEMM_SMEM);

    k_csr<<<BB, EPG>>>(ei);
    k_prepW<<<64, 256>>>(Wre2, Wro2, Wre3, Wro3);

    k_layer1<<<BB, 256>>>(x, Wre1, Wro1, b1);                 // -> g_HA

    k_gemm<<<296, 256, GEMM_SMEM>>>(2, b2);                   // g_HA -> g_P, g_Rb
    k_conv<<<BB, 544>>>(2);                                   // -> g_HB

    k_gemm<<<296, 256, GEMM_SMEM>>>(3, b3);                   // g_HB -> g_P, g_Rb
    k_conv<<<BB, 544>>>(3);                                   // -> g_HA

    k_pool<<<BB, 512>>>(s_in, fcw, fcb, out);
}